// round 2
// baseline (speedup 1.0000x reference)
#include <cuda_runtime.h>
#include <math.h>

#define D 1024
#define F 4096
#define E 8
#define T 2048
#define CAP 2048   // worst case: every token picks this expert (distinct experts per token)

// -------- scratch (device globals; no allocations allowed) --------
__device__ int   g_count[E];
__device__ int   g_tok[E * CAP];
__device__ float g_wgt[E * CAP];
__device__ float g_h[(size_t)E * CAP * F];   // 256 MiB fp32 hidden activations

// -------- zero/init --------
__global__ void zero_kernel(float* __restrict__ out) {
    int i = blockIdx.x * blockDim.x + threadIdx.x;
    if (i < T * D) out[i] = 0.0f;
    if (i < E) g_count[i] = 0;
}

// -------- router: logits = x @ Wr + br, softmax, top-2, renormalize --------
__global__ void router_kernel(const float* __restrict__ x,
                              const float* __restrict__ Wr,
                              const float* __restrict__ br) {
    int t = blockIdx.x;        // one warp-block per token
    int lane = threadIdx.x;    // 32 threads
    float acc[E];
#pragma unroll
    for (int e = 0; e < E; e++) acc[e] = 0.0f;
    const float* xr = x + (size_t)t * D;
    for (int d = lane; d < D; d += 32) {
        float xv = xr[d];
        const float* wr = Wr + (size_t)d * E;
#pragma unroll
        for (int e = 0; e < E; e++) acc[e] += xv * wr[e];
    }
#pragma unroll
    for (int e = 0; e < E; e++) {
#pragma unroll
        for (int off = 16; off > 0; off >>= 1)
            acc[e] += __shfl_xor_sync(0xffffffffu, acc[e], off);
    }
    if (lane == 0) {
#pragma unroll
        for (int e = 0; e < E; e++) acc[e] += br[e];
        // top-2 with tie-break to lower index (matches lax.top_k)
        int i0 = 0;
#pragma unroll
        for (int e = 1; e < E; e++) if (acc[e] > acc[i0]) i0 = e;
        int i1 = (i0 == 0) ? 1 : 0;
#pragma unroll
        for (int e = 0; e < E; e++) {
            if (e == i0) continue;
            if (acc[e] > acc[i1] || (acc[e] == acc[i1] && e < i1)) i1 = e;
        }
        // renormalized top-2 softmax weights == softmax over the two logits
        float l0 = acc[i0], l1 = acc[i1];
        float e1 = expf(l1 - l0);           // <= 1
        float w0 = 1.0f / (1.0f + e1);
        float w1 = e1 * w0;
        int p0 = atomicAdd(&g_count[i0], 1);
        g_tok[i0 * CAP + p0] = t;  g_wgt[i0 * CAP + p0] = w0;
        int p1 = atomicAdd(&g_count[i1], 1);
        g_tok[i1 * CAP + p1] = t;  g_wgt[i1 * CAP + p1] = w1;
    }
}

// -------- tiled SGEMM config --------
#define BM 128
#define BN 128
#define BK 8
#define TM 8
#define TN 8
// 256 threads, each computes an 8x8 micro-tile

// GEMM1: h[e-rows] = gelu( gather(x) @ W1[e] + b1[e] )
__global__ __launch_bounds__(256) void ffn1_kernel(const float* __restrict__ x,
                                                   const float* __restrict__ W1,
                                                   const float* __restrict__ b1) {
    int e = blockIdx.z;
    int ne = g_count[e];
    int m0 = blockIdx.y * BM;
    if (m0 >= ne) return;
    int n0 = blockIdx.x * BN;

    __shared__ float As[BK][BM];
    __shared__ float Bs[BK][BN];
    __shared__ int   rows[BM];

    int tid = threadIdx.x;
    if (tid < BM) {
        int m = m0 + tid;
        rows[tid] = (m < ne) ? g_tok[e * CAP + m] : -1;
    }
    __syncthreads();

    float acc[TM][TN];
#pragma unroll
    for (int i = 0; i < TM; i++)
#pragma unroll
        for (int j = 0; j < TN; j++) acc[i][j] = 0.0f;

    const float* B = W1 + (size_t)e * D * F;
    int arow = tid >> 1;          // 0..127
    int acol = (tid & 1) * 4;     // 0 or 4
    int brow = tid >> 5;          // 0..7
    int bcol = (tid & 31) * 4;
    int ty = tid >> 4, tx = tid & 15;

    for (int k0 = 0; k0 < D; k0 += BK) {
        float4 av = make_float4(0.f, 0.f, 0.f, 0.f);
        int r = rows[arow];
        if (r >= 0) av = *(const float4*)(x + (size_t)r * D + k0 + acol);
        As[acol + 0][arow] = av.x; As[acol + 1][arow] = av.y;
        As[acol + 2][arow] = av.z; As[acol + 3][arow] = av.w;
        float4 bv = *(const float4*)(B + (size_t)(k0 + brow) * F + n0 + bcol);
        *(float4*)&Bs[brow][bcol] = bv;
        __syncthreads();
#pragma unroll
        for (int kk = 0; kk < BK; kk++) {
            float ar[TM], bw[TN];
#pragma unroll
            for (int i = 0; i < TM; i++) ar[i] = As[kk][ty * TM + i];
#pragma unroll
            for (int j = 0; j < TN; j++) bw[j] = Bs[kk][tx * TN + j];
#pragma unroll
            for (int i = 0; i < TM; i++)
#pragma unroll
                for (int j = 0; j < TN; j++) acc[i][j] += ar[i] * bw[j];
        }
        __syncthreads();
    }

    float* hbase = g_h + (size_t)e * CAP * F;
#pragma unroll
    for (int i = 0; i < TM; i++) {
        int m = m0 + ty * TM + i;
        if (m >= ne) continue;
        float* hr = hbase + (size_t)m * F + n0;
#pragma unroll
        for (int j = 0; j < TN; j++) {
            int n = tx * TN + j;
            float v = acc[i][j] + b1[e * F + n0 + n];
            v = 0.5f * v * (1.0f + erff(v * 0.70710678118654752f));  // exact GELU
            hr[n] = v;
        }
    }
}

// GEMM2: out[t] += w * ( h @ W2[e] + b2[e] )
__global__ __launch_bounds__(256) void ffn2_kernel(const float* __restrict__ W2,
                                                   const float* __restrict__ b2,
                                                   float* __restrict__ out) {
    int e = blockIdx.z;
    int ne = g_count[e];
    int m0 = blockIdx.y * BM;
    if (m0 >= ne) return;
    int n0 = blockIdx.x * BN;   // D/BN = 8 tiles

    __shared__ float As[BK][BM];
    __shared__ float Bs[BK][BN];

    int tid = threadIdx.x;
    float acc[TM][TN];
#pragma unroll
    for (int i = 0; i < TM; i++)
#pragma unroll
        for (int j = 0; j < TN; j++) acc[i][j] = 0.0f;

    const float* A = g_h + (size_t)e * CAP * F;
    const float* B = W2 + (size_t)e * F * D;
    int arow = tid >> 1;
    int acol = (tid & 1) * 4;
    int brow = tid >> 5;
    int bcol = (tid & 31) * 4;
    int ty = tid >> 4, tx = tid & 15;

    for (int k0 = 0; k0 < F; k0 += BK) {
        float4 av = make_float4(0.f, 0.f, 0.f, 0.f);
        if (m0 + arow < ne) av = *(const float4*)(A + (size_t)(m0 + arow) * F + k0 + acol);
        As[acol + 0][arow] = av.x; As[acol + 1][arow] = av.y;
        As[acol + 2][arow] = av.z; As[acol + 3][arow] = av.w;
        float4 bv = *(const float4*)(B + (size_t)(k0 + brow) * D + n0 + bcol);
        *(float4*)&Bs[brow][bcol] = bv;
        __syncthreads();
#pragma unroll
        for (int kk = 0; kk < BK; kk++) {
            float ar[TM], bw[TN];
#pragma unroll
            for (int i = 0; i < TM; i++) ar[i] = As[kk][ty * TM + i];
#pragma unroll
            for (int j = 0; j < TN; j++) bw[j] = Bs[kk][tx * TN + j];
#pragma unroll
            for (int i = 0; i < TM; i++)
#pragma unroll
                for (int j = 0; j < TN; j++) acc[i][j] += ar[i] * bw[j];
        }
        __syncthreads();
    }

#pragma unroll
    for (int i = 0; i < TM; i++) {
        int m = m0 + ty * TM + i;
        if (m >= ne) continue;
        int t = g_tok[e * CAP + m];
        float w = g_wgt[e * CAP + m];
        float* orow = out + (size_t)t * D + n0;
#pragma unroll
        for (int j = 0; j < TN; j++) {
            int n = tx * TN + j;
            float v = w * (acc[i][j] + b2[e * D + n0 + n]);
            atomicAdd(&orow[n], v);
        }
    }
}

extern "C" void kernel_launch(void* const* d_in, const int* in_sizes, int n_in,
                              void* d_out, int out_size) {
    const float* x  = (const float*)d_in[0];
    const float* Wr = (const float*)d_in[1];
    const float* br = (const float*)d_in[2];
    const float* W1 = (const float*)d_in[3];
    const float* b1 = (const float*)d_in[4];
    const float* W2 = (const float*)d_in[5];
    const float* b2 = (const float*)d_in[6];
    float* out = (float*)d_out;

    zero_kernel<<<(T * D + 255) / 256, 256>>>(out);
    router_kernel<<<T, 32>>>(x, Wr, br);
    ffn1_kernel<<<dim3(F / BN, CAP / BM, E), 256>>>(x, W1, b1);
    ffn2_kernel<<<dim3(D / BN, CAP / BM, E), 256>>>(W2, b2, out);
}

// round 8
// speedup vs baseline: 1.8231x; 1.8231x over previous
#include <cuda_runtime.h>
#include <cuda_bf16.h>
#include <math.h>
#include <stdint.h>

#define ND 1024
#define NF 4096
#define NE 8
#define NT 2048
#define NCAP 2048
#define TBM 128
#define TBN 128
#define TBK 32
#define NTHREADS 256
#define SASTR 40   // smem row stride in bf16 elems (80B) -> conflict-light

// -------- scratch (device globals; no allocations allowed) --------
__device__ int   g_count[NE];
__device__ int   g_tok[NE * NCAP];
__device__ float g_wgt[NE * NCAP];
__device__ float g_h[(size_t)NE * NCAP * NF];   // hidden activations fp32

// ==================== helpers ====================

// warp mma: D(16x8,f32) += A(16x16,bf16,row) * B(16x8,bf16,col)
__device__ __forceinline__ void mma16816(float* c, const uint32_t* a, const uint32_t* b) {
    asm volatile(
        "mma.sync.aligned.m16n8k16.row.col.f32.bf16.bf16.f32 "
        "{%0,%1,%2,%3}, {%4,%5,%6,%7}, {%8,%9}, {%0,%1,%2,%3};"
        : "+f"(c[0]), "+f"(c[1]), "+f"(c[2]), "+f"(c[3])
        : "r"(a[0]), "r"(a[1]), "r"(a[2]), "r"(a[3]), "r"(b[0]), "r"(b[1]));
}

// split 8 fp32 -> bf16 hi (uint4) + bf16 lo (uint4)
__device__ __forceinline__ void split8(const float* f, uint4& hi, uint4& lo) {
    unsigned short hs[8], ls[8];
#pragma unroll
    for (int i = 0; i < 8; i++) {
        __nv_bfloat16 h = __float2bfloat16_rn(f[i]);
        hs[i] = *reinterpret_cast<unsigned short*>(&h);
        float r = f[i] - __bfloat162float(h);
        __nv_bfloat16 l = __float2bfloat16_rn(r);
        ls[i] = *reinterpret_cast<unsigned short*>(&l);
    }
    hi.x = (uint32_t)hs[0] | ((uint32_t)hs[1] << 16);
    hi.y = (uint32_t)hs[2] | ((uint32_t)hs[3] << 16);
    hi.z = (uint32_t)hs[4] | ((uint32_t)hs[5] << 16);
    hi.w = (uint32_t)hs[6] | ((uint32_t)hs[7] << 16);
    lo.x = (uint32_t)ls[0] | ((uint32_t)ls[1] << 16);
    lo.y = (uint32_t)ls[2] | ((uint32_t)ls[3] << 16);
    lo.z = (uint32_t)ls[4] | ((uint32_t)ls[5] << 16);
    lo.w = (uint32_t)ls[6] | ((uint32_t)ls[7] << 16);
}

// ==================== small kernels ====================

__global__ void zero_kernel(float* __restrict__ out) {
    int i = blockIdx.x * blockDim.x + threadIdx.x;
    if (i < NT * ND) out[i] = 0.0f;
    if (i < NE) g_count[i] = 0;
}

__global__ void router_kernel(const float* __restrict__ x,
                              const float* __restrict__ Wr,
                              const float* __restrict__ br) {
    int t = blockIdx.x;
    int lane = threadIdx.x;
    float acc[NE];
#pragma unroll
    for (int e = 0; e < NE; e++) acc[e] = 0.0f;
    const float* xr = x + (size_t)t * ND;
    for (int d = lane; d < ND; d += 32) {
        float xv = xr[d];
        const float* wr = Wr + (size_t)d * NE;
#pragma unroll
        for (int e = 0; e < NE; e++) acc[e] += xv * wr[e];
    }
#pragma unroll
    for (int e = 0; e < NE; e++) {
#pragma unroll
        for (int off = 16; off > 0; off >>= 1)
            acc[e] += __shfl_xor_sync(0xffffffffu, acc[e], off);
    }
    if (lane == 0) {
#pragma unroll
        for (int e = 0; e < NE; e++) acc[e] += br[e];
        int i0 = 0;
#pragma unroll
        for (int e = 1; e < NE; e++) if (acc[e] > acc[i0]) i0 = e;
        int i1 = (i0 == 0) ? 1 : 0;
#pragma unroll
        for (int e = 0; e < NE; e++) {
            if (e == i0) continue;
            if (acc[e] > acc[i1] || (acc[e] == acc[i1] && e < i1)) i1 = e;
        }
        float l0 = acc[i0], l1 = acc[i1];
        float e1 = expf(l1 - l0);
        float w0 = 1.0f / (1.0f + e1);
        float w1 = e1 * w0;
        int p0 = atomicAdd(&g_count[i0], 1);
        g_tok[i0 * NCAP + p0] = t;  g_wgt[i0 * NCAP + p0] = w0;
        int p1 = atomicAdd(&g_count[i1], 1);
        g_tok[i1 * NCAP + p1] = t;  g_wgt[i1 * NCAP + p1] = w1;
    }
}

// ==================== split-bf16 HMMA GEMM ====================
// Tile: 128x128, BK=32. 8 warps, each 64x32 (4x4 m16n8k16 tiles).
// smem: Ah/Al [128][SASTR], Bh/Bl [128][SASTR] (B stored [n][k]).

__global__ __launch_bounds__(NTHREADS, 2) void moe_mma_gemm(
    const float* __restrict__ x,
    const float* __restrict__ W,
    const float* __restrict__ bias,
    float* __restrict__ out,
    int kdim, int ldb, int is_ffn1)
{
    int e = blockIdx.z;
    int ne = g_count[e];
    int m0 = blockIdx.y * TBM;
    if (m0 >= ne) return;
    int n0 = blockIdx.x * TBN;
    int tid = threadIdx.x;
    int warp = tid >> 5;
    int lane = tid & 31;
    int wm = warp >> 2;          // 0..1 -> m offset wm*64
    int wn = warp & 3;           // 0..3 -> n offset wn*32
    int grp = lane >> 2;         // 0..7
    int tig = lane & 3;          // 0..3

    __shared__ __nv_bfloat16 Ah[TBM * SASTR];
    __shared__ __nv_bfloat16 Al[TBM * SASTR];
    __shared__ __nv_bfloat16 Bh[TBN * SASTR];
    __shared__ __nv_bfloat16 Bl[TBN * SASTR];
    __shared__ int rows[TBM];

    if (is_ffn1 && tid < TBM) {
        int m = m0 + tid;
        rows[tid] = (m < ne) ? g_tok[e * NCAP + m] : -1;
    }
    __syncthreads();

    const float* Wbase = W + (size_t)e * (size_t)kdim * (size_t)ldb;
    const float* Hread = g_h + (size_t)e * NCAP * NF;
    float*       Hwrite = g_h + (size_t)e * NCAP * NF;

    float acc[4][4][4];
#pragma unroll
    for (int i = 0; i < 4; i++)
#pragma unroll
        for (int j = 0; j < 4; j++)
#pragma unroll
            for (int q = 0; q < 4; q++) acc[i][j][q] = 0.0f;

    for (int k0 = 0; k0 < kdim; k0 += TBK) {
        // ---- fill A: 128 rows x 32 k (512 units of 8) ----
#pragma unroll
        for (int uu = 0; uu < 2; uu++) {
            int u = tid + uu * NTHREADS;
            int row = u >> 2;
            int part = u & 3;
            float fv[8];
#pragma unroll
            for (int i = 0; i < 8; i++) fv[i] = 0.0f;
            if (is_ffn1) {
                int tokr = rows[row];
                if (tokr >= 0) {
                    const float* s = x + (size_t)tokr * ND + k0 + part * 8;
#pragma unroll
                    for (int i = 0; i < 8; i++) fv[i] = s[i];
                }
            } else {
                if (m0 + row < ne) {
                    const float* s = Hread + (size_t)(m0 + row) * NF + k0 + part * 8;
#pragma unroll
                    for (int i = 0; i < 8; i++) fv[i] = s[i];
                }
            }
            uint4 hi, lo;
            split8(fv, hi, lo);
            int off = row * SASTR + part * 8;
            *(uint4*)(Ah + off) = hi;
            *(uint4*)(Al + off) = lo;
        }
        // ---- fill B: [n][k], source W[k][n] ----
#pragma unroll
        for (int uu = 0; uu < 2; uu++) {
            int u = tid + uu * NTHREADS;
            int n = u & 127;
            int part = u >> 7;
            const float* s = Wbase + (size_t)(k0 + part * 8) * ldb + n0 + n;
            float fv[8];
#pragma unroll
            for (int kk = 0; kk < 8; kk++) fv[kk] = s[(size_t)kk * ldb];
            uint4 hi, lo;
            split8(fv, hi, lo);
            int off = n * SASTR + part * 8;
            *(uint4*)(Bh + off) = hi;
            *(uint4*)(Bl + off) = lo;
        }
        __syncthreads();

        // ---- compute: 2 k16 steps ----
#pragma unroll
        for (int s = 0; s < 2; s++) {
            int ks = s * 16;
            uint32_t bh[4][2], bl[4][2];
#pragma unroll
            for (int nt = 0; nt < 4; nt++) {
                int n = wn * 32 + nt * 8 + grp;
                int kc = ks + tig * 2;
                bh[nt][0] = *(const uint32_t*)(Bh + n * SASTR + kc);
                bh[nt][1] = *(const uint32_t*)(Bh + n * SASTR + kc + 8);
                bl[nt][0] = *(const uint32_t*)(Bl + n * SASTR + kc);
                bl[nt][1] = *(const uint32_t*)(Bl + n * SASTR + kc + 8);
            }
#pragma unroll
            for (int mt = 0; mt < 4; mt++) {
                int m = wm * 64 + mt * 16 + grp;
                int kc = ks + tig * 2;
                uint32_t ah[4], al[4];
                ah[0] = *(const uint32_t*)(Ah + m * SASTR + kc);
                ah[1] = *(const uint32_t*)(Ah + (m + 8) * SASTR + kc);
                ah[2] = *(const uint32_t*)(Ah + m * SASTR + kc + 8);
                ah[3] = *(const uint32_t*)(Ah + (m + 8) * SASTR + kc + 8);
                al[0] = *(const uint32_t*)(Al + m * SASTR + kc);
                al[1] = *(const uint32_t*)(Al + (m + 8) * SASTR + kc);
                al[2] = *(const uint32_t*)(Al + m * SASTR + kc + 8);
                al[3] = *(const uint32_t*)(Al + (m + 8) * SASTR + kc + 8);
#pragma unroll
                for (int nt = 0; nt < 4; nt++) {
                    mma16816(acc[mt][nt], ah, bh[nt]);
                    mma16816(acc[mt][nt], ah, bl[nt]);
                    mma16816(acc[mt][nt], al, bh[nt]);
                }
            }
        }
        __syncthreads();
    }

    // ---- epilogue (single clean writeback path) ----
    // c0,c1 -> (row grp, cols tig*2, tig*2+1); c2,c3 -> (row grp+8, same cols)
#pragma unroll
    for (int mt = 0; mt < 4; mt++) {
#pragma unroll
        for (int half = 0; half < 2; half++) {
            int m = m0 + wm * 64 + mt * 16 + grp + half * 8;
            if (m >= ne) continue;
            if (is_ffn1) {
                float* hr = Hwrite + (size_t)m * NF;
                const float* bb = bias + (size_t)e * NF;
#pragma unroll
                for (int nt = 0; nt < 4; nt++) {
                    int n = n0 + wn * 32 + nt * 8 + tig * 2;
                    float v0 = acc[mt][nt][half * 2 + 0] + bb[n];
                    float v1 = acc[mt][nt][half * 2 + 1] + bb[n + 1];
                    v0 = 0.5f * v0 * (1.0f + erff(v0 * 0.70710678118654752f));
                    v1 = 0.5f * v1 * (1.0f + erff(v1 * 0.70710678118654752f));
                    hr[n] = v0;
                    hr[n + 1] = v1;
                }
            } else {
                int tok = g_tok[e * NCAP + m];
                float wgt = g_wgt[e * NCAP + m];
                float* orow = out + (size_t)tok * ND;
                const float* bb = bias + (size_t)e * ND;
#pragma unroll
                for (int nt = 0; nt < 4; nt++) {
                    int n = n0 + wn * 32 + nt * 8 + tig * 2;
                    float v0 = wgt * (acc[mt][nt][half * 2 + 0] + bb[n]);
                    float v1 = wgt * (acc[mt][nt][half * 2 + 1] + bb[n + 1]);
                    atomicAdd(&orow[n], v0);
                    atomicAdd(&orow[n + 1], v1);
                }
            }
        }
    }
}

// ==================== host launcher ====================

extern "C" void kernel_launch(void* const* d_in, const int* in_sizes, int n_in,
                              void* d_out, int out_size) {
    const float* x  = (const float*)d_in[0];
    const float* Wr = (const float*)d_in[1];
    const float* br = (const float*)d_in[2];
    const float* W1 = (const float*)d_in[3];
    const float* b1 = (const float*)d_in[4];
    const float* W2 = (const float*)d_in[5];
    const float* b2 = (const float*)d_in[6];
    float* out = (float*)d_out;

    zero_kernel<<<(NT * ND + 255) / 256, 256>>>(out);
    router_kernel<<<NT, 32>>>(x, Wr, br);
    moe_mma_gemm<<<dim3(NF / TBN, NCAP / TBM, NE), NTHREADS>>>(
        x, W1, b1, out, ND, NF, 1);
    moe_mma_gemm<<<dim3(ND / TBN, NCAP / TBM, NE), NTHREADS>>>(
        x, W2, b2, out, NF, ND, 0);
}

// round 9
// speedup vs baseline: 2.3854x; 1.3084x over previous
#include <cuda_runtime.h>
#include <cuda_bf16.h>
#include <math.h>
#include <stdint.h>

#define ND 1024
#define NF 4096
#define NE 8
#define NT 2048
#define NCAP 2048
#define TBM 128
#define TBN 128
#define TBK 32
#define NTHREADS 256
#define SASTR 40     // smem row stride in bf16 elems (80B): conflict-light, 16B-aligned

// -------- scratch (device globals; no allocations allowed) --------
__device__ int   g_count[NE];
__device__ int   g_tok[NE * NCAP];
__device__ float g_wgt[NE * NCAP];
// split-bf16 operand storage
__device__ __nv_bfloat16 g_xh[(size_t)NT * ND];
__device__ __nv_bfloat16 g_xl[(size_t)NT * ND];
__device__ __nv_bfloat16 g_w1h[(size_t)NE * ND * NF];  // layout [e][n(F)][k(D)]
__device__ __nv_bfloat16 g_w1l[(size_t)NE * ND * NF];
__device__ __nv_bfloat16 g_w2h[(size_t)NE * NF * ND];  // layout [e][n(D)][k(F)]
__device__ __nv_bfloat16 g_w2l[(size_t)NE * NF * ND];
__device__ __nv_bfloat16 g_hh[(size_t)NE * NCAP * NF]; // hidden, split bf16
__device__ __nv_bfloat16 g_hl[(size_t)NE * NCAP * NF];

// ==================== helpers ====================

__device__ __forceinline__ uint32_t smem_to_u32(const void* smem_ptr) {
    uint32_t addr;
    asm("{ .reg .u64 tmp; cvta.to.shared.u64 tmp, %1; cvt.u32.u64 %0, tmp; }"
        : "=r"(addr) : "l"(smem_ptr));
    return addr;
}

__device__ __forceinline__ void cp16(uint32_t smem_dst, const void* gsrc) {
    size_t gaddr = __cvta_generic_to_global(gsrc);
    asm volatile("cp.async.cg.shared.global [%0], [%1], 16;"
                 :: "r"(smem_dst), "l"(gaddr) : "memory");
}
#define CP_COMMIT() asm volatile("cp.async.commit_group;" ::: "memory")
template<int N>
__device__ __forceinline__ void cp_wait() {
    asm volatile("cp.async.wait_group %0;" :: "n"(N) : "memory");
}

// warp mma: D(16x8,f32) += A(16x16,bf16,row) * B(16x8,bf16,col)
__device__ __forceinline__ void mma16816(float* c, const uint32_t* a, const uint32_t* b) {
    asm volatile(
        "mma.sync.aligned.m16n8k16.row.col.f32.bf16.bf16.f32 "
        "{%0,%1,%2,%3}, {%4,%5,%6,%7}, {%8,%9}, {%0,%1,%2,%3};"
        : "+f"(c[0]), "+f"(c[1]), "+f"(c[2]), "+f"(c[3])
        : "r"(a[0]), "r"(a[1]), "r"(a[2]), "r"(a[3]), "r"(b[0]), "r"(b[1]));
}

// split 8 fp32 -> bf16 hi (uint4) + bf16 lo (uint4)
__device__ __forceinline__ void split8(const float* f, uint4& hi, uint4& lo) {
    unsigned short hs[8], ls[8];
#pragma unroll
    for (int i = 0; i < 8; i++) {
        __nv_bfloat16 h = __float2bfloat16_rn(f[i]);
        hs[i] = *reinterpret_cast<unsigned short*>(&h);
        float r = f[i] - __bfloat162float(h);
        __nv_bfloat16 l = __float2bfloat16_rn(r);
        ls[i] = *reinterpret_cast<unsigned short*>(&l);
    }
    hi.x = (uint32_t)hs[0] | ((uint32_t)hs[1] << 16);
    hi.y = (uint32_t)hs[2] | ((uint32_t)hs[3] << 16);
    hi.z = (uint32_t)hs[4] | ((uint32_t)hs[5] << 16);
    hi.w = (uint32_t)hs[6] | ((uint32_t)hs[7] << 16);
    lo.x = (uint32_t)ls[0] | ((uint32_t)ls[1] << 16);
    lo.y = (uint32_t)ls[2] | ((uint32_t)ls[3] << 16);
    lo.z = (uint32_t)ls[4] | ((uint32_t)ls[5] << 16);
    lo.w = (uint32_t)ls[6] | ((uint32_t)ls[7] << 16);
}

__device__ __forceinline__ uint32_t pack_bf16x2(__nv_bfloat16 a, __nv_bfloat16 b) {
    unsigned short sa = *reinterpret_cast<unsigned short*>(&a);
    unsigned short sb = *reinterpret_cast<unsigned short*>(&b);
    return (uint32_t)sa | ((uint32_t)sb << 16);
}

// ==================== precompute kernels ====================

__global__ void zero_kernel(float* __restrict__ out) {
    int i = blockIdx.x * blockDim.x + threadIdx.x;
    if (i < NT * ND) out[i] = 0.0f;
    if (i < NE) g_count[i] = 0;
}

__global__ void splitx_kernel(const float* __restrict__ x) {
    int i = blockIdx.x * blockDim.x + threadIdx.x;   // pair index
    if (i < NT * ND / 2) {
        float2 v = ((const float2*)x)[i];
        __nv_bfloat16 h0 = __float2bfloat16_rn(v.x);
        __nv_bfloat16 h1 = __float2bfloat16_rn(v.y);
        float r0 = v.x - __bfloat162float(h0);
        float r1 = v.y - __bfloat162float(h1);
        __nv_bfloat16 l0 = __float2bfloat16_rn(r0);
        __nv_bfloat16 l1 = __float2bfloat16_rn(r1);
        ((uint32_t*)g_xh)[i] = pack_bf16x2(h0, h1);
        ((uint32_t*)g_xl)[i] = pack_bf16x2(l0, l1);
    }
}

// transpose+split W[e][k][n] fp32 -> Wh/Wl [e][n][k] bf16
__global__ void splitw_kernel(const float* __restrict__ Wsrc,
                              int kdim, int ndim, int which) {
    __shared__ float tile[64][65];
    int e = blockIdx.z;
    int n0 = blockIdx.x * 64;
    int k0 = blockIdx.y * 64;
    int tid = threadIdx.x;
    const float* src = Wsrc + (size_t)e * (size_t)kdim * (size_t)ndim;
#pragma unroll
    for (int i = 0; i < 16; i++) {
        int r = (tid >> 6) + i * 4;
        int c = tid & 63;
        tile[r][c] = src[(size_t)(k0 + r) * ndim + n0 + c];
    }
    __syncthreads();
    __nv_bfloat16* Wh = which ? g_w1h : g_w2h;
    __nv_bfloat16* Wl = which ? g_w1l : g_w2l;
    size_t base = (size_t)e * (size_t)kdim * (size_t)ndim;
    int nl = tid >> 2;
    int kq = (tid & 3) * 16;
#pragma unroll
    for (int half = 0; half < 2; half++) {
        float fv[8];
#pragma unroll
        for (int j = 0; j < 8; j++) fv[j] = tile[kq + half * 8 + j][nl];
        uint4 hi, lo;
        split8(fv, hi, lo);
        size_t o = base + (size_t)(n0 + nl) * kdim + k0 + kq + half * 8;
        *(uint4*)(Wh + o) = hi;
        *(uint4*)(Wl + o) = lo;
    }
}

__global__ void router_kernel(const float* __restrict__ x,
                              const float* __restrict__ Wr,
                              const float* __restrict__ br) {
    int t = blockIdx.x;
    int lane = threadIdx.x;
    float acc[NE];
#pragma unroll
    for (int e = 0; e < NE; e++) acc[e] = 0.0f;
    const float* xr = x + (size_t)t * ND;
    for (int d = lane; d < ND; d += 32) {
        float xv = xr[d];
        const float* wr = Wr + (size_t)d * NE;
#pragma unroll
        for (int e = 0; e < NE; e++) acc[e] += xv * wr[e];
    }
#pragma unroll
    for (int e = 0; e < NE; e++) {
#pragma unroll
        for (int off = 16; off > 0; off >>= 1)
            acc[e] += __shfl_xor_sync(0xffffffffu, acc[e], off);
    }
    if (lane == 0) {
#pragma unroll
        for (int e = 0; e < NE; e++) acc[e] += br[e];
        int i0 = 0;
#pragma unroll
        for (int e = 1; e < NE; e++) if (acc[e] > acc[i0]) i0 = e;
        int i1 = (i0 == 0) ? 1 : 0;
#pragma unroll
        for (int e = 0; e < NE; e++) {
            if (e == i0) continue;
            if (acc[e] > acc[i1] || (acc[e] == acc[i1] && e < i1)) i1 = e;
        }
        float l0 = acc[i0], l1 = acc[i1];
        float e1 = expf(l1 - l0);
        float w0 = 1.0f / (1.0f + e1);
        float w1 = e1 * w0;
        int p0 = atomicAdd(&g_count[i0], 1);
        g_tok[i0 * NCAP + p0] = t;  g_wgt[i0 * NCAP + p0] = w0;
        int p1 = atomicAdd(&g_count[i1], 1);
        g_tok[i1 * NCAP + p1] = t;  g_wgt[i1 * NCAP + p1] = w1;
    }
}

// ==================== split-bf16 HMMA GEMM, cp.async double-buffered ====================
// smem per stage: Ah[10240] Al[10240] Bh[10240] Bl[10240] = 40960B; 2 stages + rows.
#define OFF_AH 0
#define OFF_AL 10240
#define OFF_BH 20480
#define OFF_BL 30720
#define STAGEB 40960
#define SMEM_REQ (2 * STAGEB + 512)

__global__ __launch_bounds__(NTHREADS, 2) void moe_mma_gemm(
    const float* __restrict__ bias,
    float* __restrict__ out,
    int kdim, int ldb, int is_ffn1)
{
    int e = blockIdx.z;
    int ne = g_count[e];
    int m0 = blockIdx.y * TBM;
    if (m0 >= ne) return;
    int n0 = blockIdx.x * TBN;
    int tid = threadIdx.x;
    int warp = tid >> 5;
    int lane = tid & 31;
    int wm = warp >> 2;
    int wn = warp & 3;
    int grp = lane >> 2;
    int tig = lane & 3;

    extern __shared__ char smbase[];
    uint32_t smu = smem_to_u32(smbase);
    int* rows = (int*)(smbase + 2 * STAGEB);

    if (is_ffn1 && tid < TBM) {
        int m = m0 + tid;
        rows[tid] = (m < ne) ? g_tok[e * NCAP + m] : -1;
    }
    __syncthreads();

    const __nv_bfloat16* Whb = (is_ffn1 ? g_w1h : g_w2h) + (size_t)e * (size_t)kdim * (size_t)ldb;
    const __nv_bfloat16* Wlb = (is_ffn1 ? g_w1l : g_w2l) + (size_t)e * (size_t)kdim * (size_t)ldb;
    const __nv_bfloat16* Ahb = is_ffn1 ? g_xh : (g_hh + (size_t)e * NCAP * NF);
    const __nv_bfloat16* Alb = is_ffn1 ? g_xl : (g_hl + (size_t)e * NCAP * NF);
    size_t arow_stride = is_ffn1 ? ND : NF;

    auto fill = [&](int s, int kb) {
        int k0 = kb * TBK;
        uint32_t sb = smu + s * STAGEB;
        char* sp = smbase + s * STAGEB;
#pragma unroll
        for (int i = 0; i < 2; i++) {
            int u = tid + i * NTHREADS;     // 0..511
            int row = u >> 2;
            int part = u & 3;
            uint32_t off = row * 80 + part * 16;
            // A operand (gathered for ffn1, direct for ffn2)
            long arow;
            if (is_ffn1) arow = rows[row];
            else         arow = (m0 + row < ne) ? (m0 + row) : -1;
            if (arow >= 0) {
                const __nv_bfloat16* sh = Ahb + (size_t)arow * arow_stride + k0 + part * 8;
                const __nv_bfloat16* sl = Alb + (size_t)arow * arow_stride + k0 + part * 8;
                cp16(sb + OFF_AH + off, sh);
                cp16(sb + OFF_AL + off, sl);
            } else {
                *(uint4*)(sp + OFF_AH + off) = make_uint4(0, 0, 0, 0);
                *(uint4*)(sp + OFF_AL + off) = make_uint4(0, 0, 0, 0);
            }
            // B operand (always valid)
            const __nv_bfloat16* bh = Whb + (size_t)(n0 + row) * kdim + k0 + part * 8;
            const __nv_bfloat16* bl = Wlb + (size_t)(n0 + row) * kdim + k0 + part * 8;
            cp16(sb + OFF_BH + off, bh);
            cp16(sb + OFF_BL + off, bl);
        }
    };

    float acc[4][4][4];
#pragma unroll
    for (int i = 0; i < 4; i++)
#pragma unroll
        for (int j = 0; j < 4; j++)
#pragma unroll
            for (int q = 0; q < 4; q++) acc[i][j][q] = 0.0f;

    int nb = kdim / TBK;
    fill(0, 0);
    CP_COMMIT();

    for (int kb = 0; kb < nb; kb++) {
        if (kb + 1 < nb) {
            fill((kb + 1) & 1, kb + 1);
            CP_COMMIT();
            cp_wait<1>();
        } else {
            cp_wait<0>();
        }
        __syncthreads();

        char* sp = smbase + (kb & 1) * STAGEB;
#pragma unroll
        for (int s = 0; s < 2; s++) {
            int ks = s * 16;
            int kc = ks + tig * 2;
            uint32_t bhf[4][2], blf[4][2];
#pragma unroll
            for (int nt = 0; nt < 4; nt++) {
                int n = wn * 32 + nt * 8 + grp;
                const char* bp = sp + n * 80 + kc * 2;
                bhf[nt][0] = *(const uint32_t*)(bp + OFF_BH);
                bhf[nt][1] = *(const uint32_t*)(bp + OFF_BH + 16);
                blf[nt][0] = *(const uint32_t*)(bp + OFF_BL);
                blf[nt][1] = *(const uint32_t*)(bp + OFF_BL + 16);
            }
#pragma unroll
            for (int mt = 0; mt < 4; mt++) {
                int m = wm * 64 + mt * 16 + grp;
                const char* ap0 = sp + m * 80 + kc * 2;
                const char* ap1 = sp + (m + 8) * 80 + kc * 2;
                uint32_t ah[4], al[4];
                ah[0] = *(const uint32_t*)(ap0 + OFF_AH);
                ah[1] = *(const uint32_t*)(ap1 + OFF_AH);
                ah[2] = *(const uint32_t*)(ap0 + OFF_AH + 16);
                ah[3] = *(const uint32_t*)(ap1 + OFF_AH + 16);
                al[0] = *(const uint32_t*)(ap0 + OFF_AL);
                al[1] = *(const uint32_t*)(ap1 + OFF_AL);
                al[2] = *(const uint32_t*)(ap0 + OFF_AL + 16);
                al[3] = *(const uint32_t*)(ap1 + OFF_AL + 16);
#pragma unroll
                for (int nt = 0; nt < 4; nt++) {
                    mma16816(acc[mt][nt], ah, bhf[nt]);
                    mma16816(acc[mt][nt], ah, blf[nt]);
                    mma16816(acc[mt][nt], al, bhf[nt]);
                }
            }
        }
        __syncthreads();
    }

    // ---- epilogue ----
#pragma unroll
    for (int mt = 0; mt < 4; mt++) {
#pragma unroll
        for (int half = 0; half < 2; half++) {
            int m = m0 + wm * 64 + mt * 16 + grp + half * 8;
            if (m >= ne) continue;
            if (is_ffn1) {
                const float* bb = bias + (size_t)e * NF;
                __nv_bfloat16* hh = g_hh + (size_t)e * NCAP * NF + (size_t)m * NF;
                __nv_bfloat16* hl = g_hl + (size_t)e * NCAP * NF + (size_t)m * NF;
#pragma unroll
                for (int nt = 0; nt < 4; nt++) {
                    int n = n0 + wn * 32 + nt * 8 + tig * 2;
                    float v0 = acc[mt][nt][half * 2 + 0] + bb[n];
                    float v1 = acc[mt][nt][half * 2 + 1] + bb[n + 1];
                    v0 = 0.5f * v0 * (1.0f + erff(v0 * 0.70710678118654752f));
                    v1 = 0.5f * v1 * (1.0f + erff(v1 * 0.70710678118654752f));
                    __nv_bfloat16 h0 = __float2bfloat16_rn(v0);
                    __nv_bfloat16 h1 = __float2bfloat16_rn(v1);
                    __nv_bfloat16 l0 = __float2bfloat16_rn(v0 - __bfloat162float(h0));
                    __nv_bfloat16 l1 = __float2bfloat16_rn(v1 - __bfloat162float(h1));
                    *(uint32_t*)(hh + n) = pack_bf16x2(h0, h1);
                    *(uint32_t*)(hl + n) = pack_bf16x2(l0, l1);
                }
            } else {
                int tok = g_tok[e * NCAP + m];
                float wgt = g_wgt[e * NCAP + m];
                float* orow = out + (size_t)tok * ND;
                const float* bb = bias + (size_t)e * ND;
#pragma unroll
                for (int nt = 0; nt < 4; nt++) {
                    int n = n0 + wn * 32 + nt * 8 + tig * 2;
                    float v0 = wgt * (acc[mt][nt][half * 2 + 0] + bb[n]);
                    float v1 = wgt * (acc[mt][nt][half * 2 + 1] + bb[n + 1]);
                    atomicAdd(&orow[n], v0);
                    atomicAdd(&orow[n + 1], v1);
                }
            }
        }
    }
}

// ==================== host launcher ====================

extern "C" void kernel_launch(void* const* d_in, const int* in_sizes, int n_in,
                              void* d_out, int out_size) {
    const float* x  = (const float*)d_in[0];
    const float* Wr = (const float*)d_in[1];
    const float* br = (const float*)d_in[2];
    const float* W1 = (const float*)d_in[3];
    const float* b1 = (const float*)d_in[4];
    const float* W2 = (const float*)d_in[5];
    const float* b2 = (const float*)d_in[6];
    float* out = (float*)d_out;

    cudaFuncSetAttribute(moe_mma_gemm,
                         cudaFuncAttributeMaxDynamicSharedMemorySize, SMEM_REQ);

    zero_kernel<<<(NT * ND + 255) / 256, 256>>>(out);
    splitx_kernel<<<(NT * ND / 2 + 255) / 256, 256>>>(x);
    // W1: kdim=ND(1024), ndim=NF(4096) -> grid (NF/64, ND/64, NE)
    splitw_kernel<<<dim3(NF / 64, ND / 64, NE), 256>>>(W1, ND, NF, 1);
    // W2: kdim=NF(4096), ndim=ND(1024)
    splitw_kernel<<<dim3(ND / 64, NF / 64, NE), 256>>>(W2, NF, ND, 0);
    router_kernel<<<NT, 32>>>(x, Wr, br);
    moe_mma_gemm<<<dim3(NF / TBN, NCAP / TBM, NE), NTHREADS, SMEM_REQ>>>(
        b1, out, ND, NF, 1);
    moe_mma_gemm<<<dim3(ND / TBN, NCAP / TBM, NE), NTHREADS, SMEM_REQ>>>(
        b2, out, NF, ND, 0);
}

// round 10
// speedup vs baseline: 3.4792x; 1.4586x over previous
#include <cuda_runtime.h>
#include <cuda_fp16.h>
#include <math.h>
#include <stdint.h>

#define ND 1024
#define NF 4096
#define NE 8
#define NT 2048
#define NCAP 2048
#define TBM 128
#define TBN 128
#define TBK 32
#define NTHREADS 256

// -------- scratch (device globals; no allocations allowed) --------
__device__ int   g_count[NE];
__device__ int   g_tok[NE * NCAP];
__device__ float g_wgt[NE * NCAP];
// split-fp16 A operands (hi+lo), single-fp16 B operands
__device__ __half g_xh[(size_t)NT * ND];
__device__ __half g_xl[(size_t)NT * ND];
__device__ __half g_w1h[(size_t)NE * ND * NF];  // [e][n(F)][k(D)]
__device__ __half g_w2h[(size_t)NE * NF * ND];  // [e][n(D)][k(F)]
__device__ __half g_hh[(size_t)NE * NCAP * NF]; // hidden hi
__device__ __half g_hl[(size_t)NE * NCAP * NF]; // hidden lo

// ==================== helpers ====================

__device__ __forceinline__ uint32_t smem_to_u32(const void* smem_ptr) {
    uint32_t addr;
    asm("{ .reg .u64 tmp; cvta.to.shared.u64 tmp, %1; cvt.u32.u64 %0, tmp; }"
        : "=r"(addr) : "l"(smem_ptr));
    return addr;
}

__device__ __forceinline__ void cp16(uint32_t smem_dst, const void* gsrc) {
    size_t gaddr = __cvta_generic_to_global(gsrc);
    asm volatile("cp.async.cg.shared.global [%0], [%1], 16;"
                 :: "r"(smem_dst), "l"(gaddr) : "memory");
}
#define CP_COMMIT() asm volatile("cp.async.commit_group;" ::: "memory")
template<int N>
__device__ __forceinline__ void cp_wait() {
    asm volatile("cp.async.wait_group %0;" :: "n"(N) : "memory");
}

// warp mma: D(16x8,f32) += A(16x16,f16,row) * B(16x8,f16,col)
__device__ __forceinline__ void mma16816h(float* c, const uint32_t* a, const uint32_t* b) {
    asm volatile(
        "mma.sync.aligned.m16n8k16.row.col.f32.f16.f16.f32 "
        "{%0,%1,%2,%3}, {%4,%5,%6,%7}, {%8,%9}, {%0,%1,%2,%3};"
        : "+f"(c[0]), "+f"(c[1]), "+f"(c[2]), "+f"(c[3])
        : "r"(a[0]), "r"(a[1]), "r"(a[2]), "r"(a[3]), "r"(b[0]), "r"(b[1]));
}

__device__ __forceinline__ uint32_t pack_h2(__half a, __half b) {
    unsigned short sa = *reinterpret_cast<unsigned short*>(&a);
    unsigned short sb = *reinterpret_cast<unsigned short*>(&b);
    return (uint32_t)sa | ((uint32_t)sb << 16);
}

// 8 fp32 -> fp16 hi (uint4) + fp16 lo (uint4)
__device__ __forceinline__ void split8h(const float* f, uint4& hi, uint4& lo) {
    unsigned short hs[8], ls[8];
#pragma unroll
    for (int i = 0; i < 8; i++) {
        __half h = __float2half_rn(f[i]);
        hs[i] = *reinterpret_cast<unsigned short*>(&h);
        float r = f[i] - __half2float(h);
        __half l = __float2half_rn(r);
        ls[i] = *reinterpret_cast<unsigned short*>(&l);
    }
    hi.x = (uint32_t)hs[0] | ((uint32_t)hs[1] << 16);
    hi.y = (uint32_t)hs[2] | ((uint32_t)hs[3] << 16);
    hi.z = (uint32_t)hs[4] | ((uint32_t)hs[5] << 16);
    hi.w = (uint32_t)hs[6] | ((uint32_t)hs[7] << 16);
    lo.x = (uint32_t)ls[0] | ((uint32_t)ls[1] << 16);
    lo.y = (uint32_t)ls[2] | ((uint32_t)ls[3] << 16);
    lo.z = (uint32_t)ls[4] | ((uint32_t)ls[5] << 16);
    lo.w = (uint32_t)ls[6] | ((uint32_t)ls[7] << 16);
}

// 8 fp32 -> fp16 (uint4), no lo
__device__ __forceinline__ void cvt8h(const float* f, uint4& hi) {
    unsigned short hs[8];
#pragma unroll
    for (int i = 0; i < 8; i++) {
        __half h = __float2half_rn(f[i]);
        hs[i] = *reinterpret_cast<unsigned short*>(&h);
    }
    hi.x = (uint32_t)hs[0] | ((uint32_t)hs[1] << 16);
    hi.y = (uint32_t)hs[2] | ((uint32_t)hs[3] << 16);
    hi.z = (uint32_t)hs[4] | ((uint32_t)hs[5] << 16);
    hi.w = (uint32_t)hs[6] | ((uint32_t)hs[7] << 16);
}

// ==================== precompute kernels ====================

__global__ void zero_kernel(float* __restrict__ out) {
    int i = blockIdx.x * blockDim.x + threadIdx.x;
    if (i < NT * ND) out[i] = 0.0f;
    if (i < NE) g_count[i] = 0;
}

__global__ void splitx_kernel(const float* __restrict__ x) {
    int i = blockIdx.x * blockDim.x + threadIdx.x;   // pair index
    if (i < NT * ND / 2) {
        float2 v = ((const float2*)x)[i];
        __half h0 = __float2half_rn(v.x);
        __half h1 = __float2half_rn(v.y);
        __half l0 = __float2half_rn(v.x - __half2float(h0));
        __half l1 = __float2half_rn(v.y - __half2float(h1));
        ((uint32_t*)g_xh)[i] = pack_h2(h0, h1);
        ((uint32_t*)g_xl)[i] = pack_h2(l0, l1);
    }
}

// transpose W[e][k][n] fp32 -> Wh [e][n][k] fp16
__global__ void splitw_kernel(const float* __restrict__ Wsrc,
                              int kdim, int ndim, int which) {
    __shared__ float tile[64][65];
    int e = blockIdx.z;
    int n0 = blockIdx.x * 64;
    int k0 = blockIdx.y * 64;
    int tid = threadIdx.x;
    const float* src = Wsrc + (size_t)e * (size_t)kdim * (size_t)ndim;
#pragma unroll
    for (int i = 0; i < 16; i++) {
        int r = (tid >> 6) + i * 4;
        int c = tid & 63;
        tile[r][c] = src[(size_t)(k0 + r) * ndim + n0 + c];
    }
    __syncthreads();
    __half* Wh = which ? g_w1h : g_w2h;
    size_t base = (size_t)e * (size_t)kdim * (size_t)ndim;
    int nl = tid >> 2;
    int kq = (tid & 3) * 16;
#pragma unroll
    for (int half = 0; half < 2; half++) {
        float fv[8];
#pragma unroll
        for (int j = 0; j < 8; j++) fv[j] = tile[kq + half * 8 + j][nl];
        uint4 hi;
        cvt8h(fv, hi);
        size_t o = base + (size_t)(n0 + nl) * kdim + k0 + kq + half * 8;
        *(uint4*)(Wh + o) = hi;
    }
}

__global__ void router_kernel(const float* __restrict__ x,
                              const float* __restrict__ Wr,
                              const float* __restrict__ br) {
    int t = blockIdx.x;
    int lane = threadIdx.x;
    float acc[NE];
#pragma unroll
    for (int e = 0; e < NE; e++) acc[e] = 0.0f;
    const float* xr = x + (size_t)t * ND;
    for (int d = lane; d < ND; d += 32) {
        float xv = xr[d];
        const float* wr = Wr + (size_t)d * NE;
#pragma unroll
        for (int e = 0; e < NE; e++) acc[e] += xv * wr[e];
    }
#pragma unroll
    for (int e = 0; e < NE; e++) {
#pragma unroll
        for (int off = 16; off > 0; off >>= 1)
            acc[e] += __shfl_xor_sync(0xffffffffu, acc[e], off);
    }
    if (lane == 0) {
#pragma unroll
        for (int e = 0; e < NE; e++) acc[e] += br[e];
        int i0 = 0;
#pragma unroll
        for (int e = 1; e < NE; e++) if (acc[e] > acc[i0]) i0 = e;
        int i1 = (i0 == 0) ? 1 : 0;
#pragma unroll
        for (int e = 0; e < NE; e++) {
            if (e == i0) continue;
            if (acc[e] > acc[i1] || (acc[e] == acc[i1] && e < i1)) i1 = e;
        }
        float l0 = acc[i0], l1 = acc[i1];
        float e1 = expf(l1 - l0);
        float w0 = 1.0f / (1.0f + e1);
        float w1 = e1 * w0;
        int p0 = atomicAdd(&g_count[i0], 1);
        g_tok[i0 * NCAP + p0] = t;  g_wgt[i0 * NCAP + p0] = w0;
        int p1 = atomicAdd(&g_count[i1], 1);
        g_tok[i1 * NCAP + p1] = t;  g_wgt[i1 * NCAP + p1] = w1;
    }
}

// ==================== split-fp16 HMMA GEMM, cp.async double-buffered ====================
// smem per stage: Ah[10240] Al[10240] Bh[10240] = 30720 B; 2 stages + rows.
#define OFF_AH 0
#define OFF_AL 10240
#define OFF_BH 20480
#define STAGEB 30720
#define SMEM_REQ (2 * STAGEB + 512)

__global__ __launch_bounds__(NTHREADS, 2) void moe_mma_gemm(
    const float* __restrict__ bias,
    float* __restrict__ out,
    int kdim, int ldb, int is_ffn1)
{
    int e = blockIdx.z;
    int ne = g_count[e];
    int m0 = blockIdx.y * TBM;
    if (m0 >= ne) return;
    int n0 = blockIdx.x * TBN;
    int tid = threadIdx.x;
    int warp = tid >> 5;
    int lane = tid & 31;
    int wm = warp >> 2;
    int wn = warp & 3;
    int grp = lane >> 2;
    int tig = lane & 3;

    extern __shared__ char smbase[];
    uint32_t smu = smem_to_u32(smbase);
    int* rows = (int*)(smbase + 2 * STAGEB);

    if (is_ffn1 && tid < TBM) {
        int m = m0 + tid;
        rows[tid] = (m < ne) ? g_tok[e * NCAP + m] : -1;
    }
    __syncthreads();

    const __half* Whb = (is_ffn1 ? g_w1h : g_w2h) + (size_t)e * (size_t)kdim * (size_t)ldb;
    const __half* Ahb = is_ffn1 ? g_xh : (g_hh + (size_t)e * NCAP * NF);
    const __half* Alb = is_ffn1 ? g_xl : (g_hl + (size_t)e * NCAP * NF);
    size_t arow_stride = is_ffn1 ? ND : NF;

    auto fill = [&](int s, int kb) {
        int k0 = kb * TBK;
        uint32_t sb = smu + s * STAGEB;
        char* sp = smbase + s * STAGEB;
#pragma unroll
        for (int i = 0; i < 2; i++) {
            int u = tid + i * NTHREADS;     // 0..511
            int row = u >> 2;
            int part = u & 3;
            uint32_t off = row * 80 + part * 16;
            long arow;
            if (is_ffn1) arow = rows[row];
            else         arow = (m0 + row < ne) ? (m0 + row) : -1;
            if (arow >= 0) {
                const __half* sh = Ahb + (size_t)arow * arow_stride + k0 + part * 8;
                const __half* sl = Alb + (size_t)arow * arow_stride + k0 + part * 8;
                cp16(sb + OFF_AH + off, sh);
                cp16(sb + OFF_AL + off, sl);
            } else {
                *(uint4*)(sp + OFF_AH + off) = make_uint4(0, 0, 0, 0);
                *(uint4*)(sp + OFF_AL + off) = make_uint4(0, 0, 0, 0);
            }
            const __half* bh = Whb + (size_t)(n0 + row) * kdim + k0 + part * 8;
            cp16(sb + OFF_BH + off, bh);
        }
    };

    float acc[4][4][4];
#pragma unroll
    for (int i = 0; i < 4; i++)
#pragma unroll
        for (int j = 0; j < 4; j++)
#pragma unroll
            for (int q = 0; q < 4; q++) acc[i][j][q] = 0.0f;

    int nb = kdim / TBK;
    fill(0, 0);
    CP_COMMIT();

    for (int kb = 0; kb < nb; kb++) {
        if (kb + 1 < nb) {
            fill((kb + 1) & 1, kb + 1);
            CP_COMMIT();
            cp_wait<1>();
        } else {
            cp_wait<0>();
        }
        __syncthreads();

        char* sp = smbase + (kb & 1) * STAGEB;
#pragma unroll
        for (int s = 0; s < 2; s++) {
            int kc = s * 16 + tig * 2;
            uint32_t bhf[4][2];
#pragma unroll
            for (int nt = 0; nt < 4; nt++) {
                int n = wn * 32 + nt * 8 + grp;
                const char* bp = sp + n * 80 + kc * 2;
                bhf[nt][0] = *(const uint32_t*)(bp + OFF_BH);
                bhf[nt][1] = *(const uint32_t*)(bp + OFF_BH + 16);
            }
#pragma unroll
            for (int mt = 0; mt < 4; mt++) {
                int m = wm * 64 + mt * 16 + grp;
                const char* ap0 = sp + m * 80 + kc * 2;
                const char* ap1 = sp + (m + 8) * 80 + kc * 2;
                uint32_t ah[4], al[4];
                ah[0] = *(const uint32_t*)(ap0 + OFF_AH);
                ah[1] = *(const uint32_t*)(ap1 + OFF_AH);
                ah[2] = *(const uint32_t*)(ap0 + OFF_AH + 16);
                ah[3] = *(const uint32_t*)(ap1 + OFF_AH + 16);
                al[0] = *(const uint32_t*)(ap0 + OFF_AL);
                al[1] = *(const uint32_t*)(ap1 + OFF_AL);
                al[2] = *(const uint32_t*)(ap0 + OFF_AL + 16);
                al[3] = *(const uint32_t*)(ap1 + OFF_AL + 16);
#pragma unroll
                for (int nt = 0; nt < 4; nt++) {
                    mma16816h(acc[mt][nt], ah, bhf[nt]);
                    mma16816h(acc[mt][nt], al, bhf[nt]);
                }
            }
        }
        __syncthreads();
    }

    // ---- epilogue ----
#pragma unroll
    for (int mt = 0; mt < 4; mt++) {
#pragma unroll
        for (int half = 0; half < 2; half++) {
            int m = m0 + wm * 64 + mt * 16 + grp + half * 8;
            if (m >= ne) continue;
            if (is_ffn1) {
                const float* bb = bias + (size_t)e * NF;
                __half* hh = g_hh + (size_t)e * NCAP * NF + (size_t)m * NF;
                __half* hl = g_hl + (size_t)e * NCAP * NF + (size_t)m * NF;
#pragma unroll
                for (int nt = 0; nt < 4; nt++) {
                    int n = n0 + wn * 32 + nt * 8 + tig * 2;
                    float v0 = acc[mt][nt][half * 2 + 0] + bb[n];
                    float v1 = acc[mt][nt][half * 2 + 1] + bb[n + 1];
                    v0 = 0.5f * v0 * (1.0f + erff(v0 * 0.70710678118654752f));
                    v1 = 0.5f * v1 * (1.0f + erff(v1 * 0.70710678118654752f));
                    __half h0 = __float2half_rn(v0);
                    __half h1 = __float2half_rn(v1);
                    __half l0 = __float2half_rn(v0 - __half2float(h0));
                    __half l1 = __float2half_rn(v1 - __half2float(h1));
                    *(uint32_t*)(hh + n) = pack_h2(h0, h1);
                    *(uint32_t*)(hl + n) = pack_h2(l0, l1);
                }
            } else {
                int tok = g_tok[e * NCAP + m];
                float wgt = g_wgt[e * NCAP + m];
                float* orow = out + (size_t)tok * ND;
                const float* bb = bias + (size_t)e * ND;
#pragma unroll
                for (int nt = 0; nt < 4; nt++) {
                    int n = n0 + wn * 32 + nt * 8 + tig * 2;
                    float v0 = wgt * (acc[mt][nt][half * 2 + 0] + bb[n]);
                    float v1 = wgt * (acc[mt][nt][half * 2 + 1] + bb[n + 1]);
                    atomicAdd(&orow[n], v0);
                    atomicAdd(&orow[n + 1], v1);
                }
            }
        }
    }
}

// ==================== host launcher ====================

extern "C" void kernel_launch(void* const* d_in, const int* in_sizes, int n_in,
                              void* d_out, int out_size) {
    const float* x  = (const float*)d_in[0];
    const float* Wr = (const float*)d_in[1];
    const float* br = (const float*)d_in[2];
    const float* W1 = (const float*)d_in[3];
    const float* b1 = (const float*)d_in[4];
    const float* W2 = (const float*)d_in[5];
    const float* b2 = (const float*)d_in[6];
    float* out = (float*)d_out;

    cudaFuncSetAttribute(moe_mma_gemm,
                         cudaFuncAttributeMaxDynamicSharedMemorySize, SMEM_REQ);

    zero_kernel<<<(NT * ND + 255) / 256, 256>>>(out);
    splitx_kernel<<<(NT * ND / 2 + 255) / 256, 256>>>(x);
    splitw_kernel<<<dim3(NF / 64, ND / 64, NE), 256>>>(W1, ND, NF, 1);
    splitw_kernel<<<dim3(ND / 64, NF / 64, NE), 256>>>(W2, NF, ND, 0);
    router_kernel<<<NT, 32>>>(x, Wr, br);
    moe_mma_gemm<<<dim3(NF / TBN, NCAP / TBM, NE), NTHREADS, SMEM_REQ>>>(
        b1, out, ND, NF, 1);
    moe_mma_gemm<<<dim3(ND / TBN, NCAP / TBM, NE), NTHREADS, SMEM_REQ>>>(
        b2, out, NF, ND, 0);
}